// round 3
// baseline (speedup 1.0000x reference)
#include <cuda_runtime.h>
#include <cuda_bf16.h>

#define TSEQ   2048
#define BATCH  4096
#define HDIM   32
#define NB     4      // batch rows per block
#define STAGE  16     // timesteps staged per x-load
#define NSTAGE (TSEQ / STAGE)
#define KHALF  16     // k-values per warp (HDIM/2)

typedef unsigned long long ull;

// ---------- packed f32x2 helpers ----------
__device__ __forceinline__ ull pack2(float lo, float hi) {
    ull r;
    asm("mov.b64 %0, {%1, %2};" : "=l"(r) : "f"(lo), "f"(hi));
    return r;
}
__device__ __forceinline__ void unpack2(ull v, float& lo, float& hi) {
    asm("mov.b64 {%0, %1}, %2;" : "=f"(lo), "=f"(hi) : "l"(v));
}
__device__ __forceinline__ ull ffma2(ull a, ull b, ull c) {
    ull d;
    asm("fma.rn.f32x2 %0, %1, %2, %3;" : "=l"(d) : "l"(a), "l"(b), "l"(c));
    return d;
}
__device__ __forceinline__ ull add2(ull a, ull b) {
    ull d;
    asm("add.rn.f32x2 %0, %1, %2;" : "=l"(d) : "l"(a), "l"(b));
    return d;
}

// ---------- single-MUFU tanh (sm_75+) ----------
__device__ __forceinline__ float tanhf_fast(float x) {
    float y;
    asm("tanh.approx.f32 %0, %1;" : "=f"(y) : "f"(x));
    return y;
}
// sigmoid(x) = 0.5*tanh(x/2) + 0.5 ; the /2 is pre-folded into weights+bias.
__device__ __forceinline__ float sig_from_half(float xh) {
    return fmaf(0.5f, tanhf_fast(xh), 0.5f);
}

// 2 warps per block, NB=4 batch rows. K-split: warp w holds W_hh columns
// k in [16w, 16w+16) (64 regs of weights). Each warp computes partial gate
// sums for all 4 batch rows, gives away partials for the 2 rows owned by the
// other warp via smem, then finishes (input affine + reduce + activations +
// h publish) for its own 2 rows. Gates packed (i,f),(g,o) into f32x2;
// sigmoid rows pre-scaled by 0.5.
__global__ void __launch_bounds__(64, 7)
lstm_ksplit_kernel(const float* __restrict__ x,
                   const float* __restrict__ W_ih,
                   const float* __restrict__ W_hh,
                   const float* __restrict__ b_ih,
                   const float* __restrict__ b_hh,
                   float* __restrict__ out)
{
    // h duplicated (v,v), double-buffered by step parity
    __shared__ __align__(16) ull hdup[2][NB][HDIM];
    // cross-warp partial sums (written for the foreign rows only)
    __shared__ __align__(16) ull part_if[NB][32];
    __shared__ __align__(16) ull part_go[NB][32];
    // x staged duplicated, double-buffered for cross-stage prefetch
    __shared__ __align__(16) ull xdup[2][NB][STAGE][4];

    const int tid   = threadIdx.x;
    const int w     = tid >> 5;      // warp id 0/1
    const int lane  = tid & 31;
    const int b0    = blockIdx.x * NB;
    const int kbase = w * KHALF;

    // PyTorch gate rows for this lane: i, f, g, o
    const int r0 = lane;             // i  (sigmoid -> 0.5 scale)
    const int r1 = HDIM + lane;      // f
    const int r2 = 2 * HDIM + lane;  // g  (tanh -> 1.0)
    const int r3 = 3 * HDIM + lane;  // o

    // ---- recurrent weights for this warp's k-half, gate-pair packed ----
    ull wif[KHALF], wgo[KHALF];
#pragma unroll
    for (int kk = 0; kk < KHALF; kk++) {
        int k = kbase + kk;
        wif[kk] = pack2(0.5f * W_hh[r0 * HDIM + k], 0.5f * W_hh[r1 * HDIM + k]);
        wgo[kk] = pack2(       W_hh[r2 * HDIM + k], 0.5f * W_hh[r3 * HDIM + k]);
    }
    // ---- input weights + combined bias (used in the owner phase) ----
    ull wxif[3], wxgo[3];
#pragma unroll
    for (int i = 0; i < 3; i++) {
        wxif[i] = pack2(0.5f * W_ih[r0 * 3 + i], 0.5f * W_ih[r1 * 3 + i]);
        wxgo[i] = pack2(       W_ih[r2 * 3 + i], 0.5f * W_ih[r3 * 3 + i]);
    }
    const ull bias_if = pack2(0.5f * (b_ih[r0] + b_hh[r0]),
                              0.5f * (b_ih[r1] + b_hh[r1]));
    const ull bias_go = pack2(       (b_ih[r2] + b_hh[r2]),
                              0.5f * (b_ih[r3] + b_hh[r3]));

    // this warp owns batch rows {2w, 2w+1}
    float c[2] = {0.0f, 0.0f};
    float h[2] = {0.0f, 0.0f};
    hdup[0][2 * w + 0][lane] = 0ull;
    hdup[0][2 * w + 1][lane] = 0ull;

    // ---- stage 0 of x: 192 floats, 3 per thread, coalesced ----
#pragma unroll
    for (int it = 0; it < 3; it++) {
        int idx = it * 64 + tid;              // 0..191
        int b   = idx / (STAGE * 3);
        int rem = idx % (STAGE * 3);
        float v = x[(size_t)(b0 + b) * TSEQ * 3 + rem];
        xdup[0][b][rem / 3][rem % 3] = pack2(v, v);
    }
    __syncthreads();

    int buf = 0;
    for (int s = 0; s < NSTAGE; s++) {
        // ---- prefetch next stage's x into registers ----
        float xr[3];
        if (s + 1 < NSTAGE) {
#pragma unroll
            for (int it = 0; it < 3; it++) {
                int idx = it * 64 + tid;
                int b   = idx / (STAGE * 3);
                int rem = idx % (STAGE * 3);
                xr[it] = x[(size_t)(b0 + b) * TSEQ * 3 + (size_t)(s + 1) * STAGE * 3 + rem];
            }
        }

#pragma unroll 1
        for (int tt = 0; tt < STAGE; tt++) {
            const int rb = tt & 1;
            const int wb = rb ^ 1;

            // ---- phase 1: partial matvec over this warp's k-half, all 4 rows ----
            ull aif[NB], ago[NB];
#pragma unroll
            for (int b = 0; b < NB; b++) { aif[b] = 0ull; ago[b] = 0ull; }

#pragma unroll
            for (int kk = 0; kk < KHALF; kk += 2) {
#pragma unroll
                for (int b = 0; b < NB; b++) {
                    ulonglong2 hd = *reinterpret_cast<const ulonglong2*>(&hdup[rb][b][kbase + kk]);
                    aif[b] = ffma2(wif[kk],     hd.x, aif[b]);
                    ago[b] = ffma2(wgo[kk],     hd.x, ago[b]);
                    aif[b] = ffma2(wif[kk + 1], hd.y, aif[b]);
                    ago[b] = ffma2(wgo[kk + 1], hd.y, ago[b]);
                }
            }

            // ---- give away partials for the foreign 2 rows ----
            {
                const int fb = (1 - w) * 2;
                part_if[fb + 0][lane] = aif[fb + 0];
                part_if[fb + 1][lane] = aif[fb + 1];
                part_go[fb + 0][lane] = ago[fb + 0];
                part_go[fb + 1][lane] = ago[fb + 1];
            }
            __syncthreads();

            // ---- phase 2: finish owned rows ----
#pragma unroll
            for (int bo = 0; bo < 2; bo++) {
                const int b = 2 * w + bo;
                ulonglong2 x01 = *reinterpret_cast<const ulonglong2*>(&xdup[buf][b][tt][0]);
                ull x2 = xdup[buf][b][tt][2];
                ull tif = ffma2(x01.x, wxif[0], ffma2(x01.y, wxif[1], ffma2(x2, wxif[2], bias_if)));
                ull tgo = ffma2(x01.x, wxgo[0], ffma2(x01.y, wxgo[1], ffma2(x2, wxgo[2], bias_go)));
                tif = add2(tif, add2(aif[b], part_if[b][lane]));
                tgo = add2(tgo, add2(ago[b], part_go[b][lane]));

                float ih, fh, gp, oh;
                unpack2(tif, ih, fh);
                unpack2(tgo, gp, oh);
                float ig = sig_from_half(ih);
                float fg = sig_from_half(fh);
                float gg = tanhf_fast(gp);
                float og = sig_from_half(oh);
                c[bo] = fmaf(fg, c[bo], ig * gg);
                h[bo] = og * tanhf_fast(c[bo]);
                hdup[wb][b][lane] = pack2(h[bo], h[bo]);
            }
            __syncthreads();
        }

        // ---- commit prefetched x into the other buffer ----
        if (s + 1 < NSTAGE) {
#pragma unroll
            for (int it = 0; it < 3; it++) {
                int idx = it * 64 + tid;
                int b   = idx / (STAGE * 3);
                int rem = idx % (STAGE * 3);
                xdup[buf ^ 1][b][rem / 3][rem % 3] = pack2(xr[it], xr[it]);
            }
            __syncthreads();
            buf ^= 1;
        }
    }

#pragma unroll
    for (int bo = 0; bo < 2; bo++)
        out[(size_t)(b0 + 2 * w + bo) * HDIM + lane] = h[bo];
}

extern "C" void kernel_launch(void* const* d_in, const int* in_sizes, int n_in,
                              void* d_out, int out_size)
{
    const float* x    = (const float*)d_in[0];
    const float* W_ih = (const float*)d_in[1];
    const float* W_hh = (const float*)d_in[2];
    const float* b_ih = (const float*)d_in[3];
    const float* b_hh = (const float*)d_in[4];
    float* out = (float*)d_out;

    lstm_ksplit_kernel<<<BATCH / NB, 64>>>(x, W_ih, W_hh, b_ih, b_hh, out);
}